// round 16
// baseline (speedup 1.0000x reference)
#include <cuda_runtime.h>
#include <cuda_fp16.h>
#include <cooperative_groups.h>
#include <math.h>

namespace cg = cooperative_groups;

#define NL   3
#define NB   64
#define NSEQ 48
#define DM   256
#define HDM  32
#define FFD  1024
#define INP  17
#define NTH  512
#define CSZ  4     // CTAs per cluster
#define RQ   64    // DM rows (Q/K/V) per CTA; also O/FF2 column-slice width
#define RF   256   // FF1 rows per CTA
#define KP   49    // padded position stride for transposed K (odd -> conflict-free)

#define CLUSTER_ARRIVE() asm volatile("barrier.cluster.arrive.aligned;" ::: "memory")
#define CLUSTER_WAIT()   asm volatile("barrier.cluster.wait.aligned;" ::: "memory")

typedef unsigned long long ull;

// ---------------- static device scratch: fp16 weights, j-pair interleaved ----------------
// Layout: [jpair][row][parity]; half2 at (jp,row) = (w[2jp][row], w[2jp+1][row]).
__device__ __align__(16) __half g_wqX[NL][CSZ][DM/2][RQ][2];
__device__ __align__(16) __half g_wkX[NL][CSZ][DM/2][RQ][2];
__device__ __align__(16) __half g_wvX[NL][CSZ][DM/2][RQ][2];
__device__ __align__(16) __half g_woX[NL][CSZ][RQ/2][DM][2];     // column-slice
__device__ __align__(16) __half g_wff1X[NL][CSZ][DM/2][RF][2];
__device__ __align__(16) __half g_wff2X[NL][CSZ][RF/2][DM][2];   // column-slice
__device__ float g_winT[INP][DM];
__device__ __align__(16) __half g_wp1X[DM/2][128][2];

// ---------------- dynamic shared-memory layout (~198 KB) ----------------
struct SMem {
    alignas(16) float xs[2][DM];        // full x, replicated
    alignas(16) float qs[2][RQ];        // local q slice
    alignas(16) float ctx[2][RQ];       // LOCAL ctx slice only
    alignas(16) float ctxp[4][2][RQ];
    alignas(16) float ffsl[2][RF];      // LOCAL ffs slice only
    alignas(16) float part[6144];
    alignas(16) float opartA[CSZ][2][DM];  // O partial-sum exchange
    alignas(16) float opartB[CSZ][2][DM];  // FF2 partial-sum exchange
    alignas(16) float sc[2][2][NSEQ];
    alignas(16) float sc2[16][NSEQ];
    alignas(16) float h1[2][128];
    float xin[2][20];
    float red[64];
    alignas(16) float kcs[NL][2][RQ][KP];     // K transposed: [local dim][pos]
    alignas(16) float vcs[NL][2][NSEQ][RQ];   // V: [pos][local dim]
};

// ---------------- prep: transpose + split + fp16-convert + j-pair interleave ----------------
__global__ void prep_kernel(const float* __restrict__ w_qkv, const float* __restrict__ w_o,
                            const float* __restrict__ w_ff1, const float* __restrict__ w_ff2,
                            const float* __restrict__ w_in,  const float* __restrict__ w_p1)
{
    int tid = blockIdx.x * blockDim.x + threadIdx.x;
    int nth = gridDim.x * blockDim.x;

    for (int i = tid; i < NL*3*DM*DM; i += nth) {
        int l = i / (3*DM*DM); int rem = i - l*3*DM*DM; int row = rem / DM; int j = rem - row*DM;
        __half v = __float2half_rn(w_qkv[i]);
        int sel = row >> 8; int rr = row & 255;
        int r = rr >> 6; int rh = rr & 63;
        if (sel == 0)      g_wqX[l][r][j>>1][rh][j&1] = v;
        else if (sel == 1) g_wkX[l][r][j>>1][rh][j&1] = v;
        else               g_wvX[l][r][j>>1][rh][j&1] = v;
    }
    for (int i = tid; i < NL*DM*DM; i += nth) {
        int l = i / (DM*DM); int rem = i - l*DM*DM; int row = rem / DM; int col = rem - row*DM;
        int r = col >> 6, jc = col & 63;
        g_woX[l][r][jc>>1][row][jc&1] = __float2half_rn(w_o[i]);
    }
    for (int i = tid; i < NL*FFD*DM; i += nth) {
        int l = i / (FFD*DM); int rem = i - l*FFD*DM; int row = rem / DM; int j = rem - row*DM;
        int r = row >> 8, rh = row & 255;
        g_wff1X[l][r][j>>1][rh][j&1] = __float2half_rn(w_ff1[i]);
    }
    for (int i = tid; i < NL*DM*FFD; i += nth) {
        int l = i / (DM*FFD); int rem = i - l*DM*FFD; int row = rem / FFD; int col = rem - row*FFD;
        int r = col >> 8, jc = col & 255;
        g_wff2X[l][r][jc>>1][row][jc&1] = __float2half_rn(w_ff2[i]);
    }
    for (int i = tid; i < DM*INP; i += nth) {
        int r = i / INP; int j = i - r*INP;
        g_winT[j][r] = w_in[i];
    }
    for (int i = tid; i < 128*DM; i += nth) {
        int row = i / DM; int j = i - row*DM;
        g_wp1X[j>>1][row][j&1] = __float2half_rn(w_p1[i]);
    }
}

// ---------------- f32x2 helpers ----------------
__device__ __forceinline__ ull h2f2p(unsigned int h2) {
    __half2 hv = *reinterpret_cast<__half2*>(&h2);
    float2 f = __half22float2(hv);
    ull p;
    asm("mov.b64 %0, {%1, %2};" : "=l"(p) : "f"(f.x), "f"(f.y));
    return p;
}
__device__ __forceinline__ void fma2(ull& d, ull a, ull b) {
    asm("fma.rn.f32x2 %0, %1, %2, %3;" : "=l"(d) : "l"(a), "l"(b), "l"(d));
}
__device__ __forceinline__ float psum(ull a) {
    float lo, hi;
    asm("mov.b64 {%0, %1}, %2;" : "=f"(lo), "=f"(hi) : "l"(a));
    return lo + hi;
}

// ---------------- weight prefetch: the two u=0 uint4s ----------------
struct PFX { uint4 a, b; };

template<int O, int I, int NACT>
__device__ __forceinline__ PFX pfx_load(const __half* __restrict__ wX, int t) {
    constexpr int G  = O / 4;
    constexpr int JC = I / (NACT / G);
    const int g = t % G;
    const int s = t / G;
    const int jb = s * JC;
    const uint4* w4 = reinterpret_cast<const uint4*>(wX);
    PFX p;
    p.a = w4[(size_t)(jb >> 1) * (O/4) + g];
    p.b = w4[(size_t)((jb >> 1) + 1) * (O/4) + g];
    return p;
}

#define FMA2_BLOCK(c0,c1,c2,c3,d0,d1,d2,d3,x0a,x1a,x0b,x1b)        \
    fma2(a0,c0,x0a); fma2(a1,c1,x0a); fma2(a2,c2,x0a); fma2(a3,c3,x0a); \
    fma2(a0,d0,x1a); fma2(a1,d1,x1a); fma2(a2,d2,x1a); fma2(a3,d3,x1a); \
    fma2(b0,c0,x0b); fma2(b1,c1,x0b); fma2(b2,c2,x0b); fma2(b3,c3,x0b); \
    fma2(b0,d0,x1b); fma2(b1,d1,x1b); fma2(b2,d2,x1b); fma2(b3,d3,x1b);

// ---------------- dual-RHS f32x2 GEMV, NACT active threads, prefetched u=0 ----
// part layout identical to previous rounds: float4 slots [s*G+g] / [NACT + s*G+g].
template<int O, int I, int NACT>
__device__ __forceinline__ void gemv2x_m(const __half* __restrict__ wX,
                                         const float* __restrict__ x0,
                                         const float* __restrict__ x1,
                                         float* __restrict__ part, int t, const PFX& pf)
{
    constexpr int G  = O / 4;
    constexpr int S  = NACT / G;
    constexpr int JC = I / S;
    const int g = t % G;
    const int s = t / G;
    const int jb = s * JC;
    const uint4* __restrict__ w4 = reinterpret_cast<const uint4*>(wX);
    ull a0=0, a1=0, a2=0, a3=0, b0=0, b1=0, b2=0, b3=0;
    {   // u = 0: prefetched weights
        ull x0a = *reinterpret_cast<const ull*>(x0 + jb);
        ull x1a = *reinterpret_cast<const ull*>(x0 + jb + 2);
        ull x0b = *reinterpret_cast<const ull*>(x1 + jb);
        ull x1b = *reinterpret_cast<const ull*>(x1 + jb + 2);
        ull c0 = h2f2p(pf.a.x), c1 = h2f2p(pf.a.y), c2 = h2f2p(pf.a.z), c3 = h2f2p(pf.a.w);
        ull d0 = h2f2p(pf.b.x), d1 = h2f2p(pf.b.y), d2 = h2f2p(pf.b.z), d3 = h2f2p(pf.b.w);
        FMA2_BLOCK(c0,c1,c2,c3,d0,d1,d2,d3,x0a,x1a,x0b,x1b)
    }
    #pragma unroll 2
    for (int u = 1; u < JC/4; ++u) {
        const int jp = (jb >> 1) + 2*u;
        uint4 W0 = w4[(size_t)jp * (O/4) + g];
        uint4 W1 = w4[(size_t)(jp + 1) * (O/4) + g];
        ull x0a = *reinterpret_cast<const ull*>(x0 + jb + 4*u);
        ull x1a = *reinterpret_cast<const ull*>(x0 + jb + 4*u + 2);
        ull x0b = *reinterpret_cast<const ull*>(x1 + jb + 4*u);
        ull x1b = *reinterpret_cast<const ull*>(x1 + jb + 4*u + 2);
        ull c0 = h2f2p(W0.x), c1 = h2f2p(W0.y), c2 = h2f2p(W0.z), c3 = h2f2p(W0.w);
        ull d0 = h2f2p(W1.x), d1 = h2f2p(W1.y), d2 = h2f2p(W1.z), d3 = h2f2p(W1.w);
        FMA2_BLOCK(c0,c1,c2,c3,d0,d1,d2,d3,x0a,x1a,x0b,x1b)
    }
    float4 A, B;
    A.x = psum(a0); A.y = psum(a1); A.z = psum(a2); A.w = psum(a3);
    B.x = psum(b0); B.y = psum(b1); B.z = psum(b2); B.w = psum(b3);
    reinterpret_cast<float4*>(part)[s*G + g]        = A;
    reinterpret_cast<float4*>(part)[NACT + s*G + g] = B;
}

__device__ __forceinline__ float gelu_exact(float x) {
    return 0.5f * x * (1.0f + erff(x * 0.70710678118654746f));
}

// ---------------- main: 4-CTA cluster per 2 batch elements ----------------
__global__ __launch_bounds__(NTH, 1) __cluster_dims__(CSZ, 1, 1)
void hedge_kernel(
    const float* __restrict__ feat,
    const float* __restrict__ b_in,
    const float* __restrict__ b_qkv,
    const float* __restrict__ b_o,
    const float* __restrict__ ln1_g, const float* __restrict__ ln1_b,
    const float* __restrict__ b_ff1, const float* __restrict__ b_ff2,
    const float* __restrict__ ln2_g, const float* __restrict__ ln2_b,
    const float* __restrict__ b_p1,
    const float* __restrict__ w_p2,  const float* __restrict__ b_p2,
    float* __restrict__ out)
{
    cg::cluster_group cl = cg::this_cluster();

    extern __shared__ __align__(16) char smem_raw[];
    SMem* sm = reinterpret_cast<SMem*>(smem_raw);
    float (&xs)[2][DM]        = sm->xs;
    float (&qs)[2][RQ]        = sm->qs;
    float (&ctx)[2][RQ]       = sm->ctx;
    float (&ctxp)[4][2][RQ]   = sm->ctxp;
    float (&ffsl)[2][RF]      = sm->ffsl;
    float (&part)[6144]       = sm->part;
    float (&opartA)[CSZ][2][DM] = sm->opartA;
    float (&opartB)[CSZ][2][DM] = sm->opartB;
    float (&sc)[2][2][NSEQ]   = sm->sc;
    float (&sc2)[16][NSEQ]    = sm->sc2;
    float (&h1)[2][128]       = sm->h1;
    float (&xin)[2][20]       = sm->xin;
    float (&red)[64]          = sm->red;

    const int cid  = blockIdx.x >> 2;
    const int r    = blockIdx.x & 3;
    const int b0   = cid * 2;
    const int t    = threadIdx.x;
    const int lane = t & 31;
    const int warp = t >> 5;

    const float PEC   = -9.210340371976184f / 256.f;   // -ln(10000)/256
    const float scale = 0.17677669529663687f;          // 1/sqrt(32)

    __syncthreads();
    cl.sync();

    // ---- prologue: token 0 input (feat + PE; delta_0 = 0) ----
    if (t < 32) {
        int e = t >> 4, j = t & 15;
        xin[e][j] = feat[((b0 + e)*NSEQ + 0)*16 + j];
    }
    __syncthreads();
    {
        int e = t >> 8, rr = t & 255;
        float acc = b_in[rr];
        #pragma unroll
        for (int j = 0; j < 16; ++j) acc = fmaf(g_winT[j][rr], xin[e][j], acc);
        acc += (rr & 1) ? 1.0f : 0.0f;   // PE at pos 0
        xs[e][rr] = acc;
    }
    __syncthreads();

    // initial QKV weight prefetch for layer 0
    PFX pfQK;
    if (t < 256) pfQK = pfx_load<RQ, DM, 256>(&g_wqX[0][r][0][0][0], t);
    else         pfQK = pfx_load<RQ, DM, 256>(&g_wkX[0][r][0][0][0], t - 256);
    PFX pfP1;

    for (int k = 0; k < NSEQ; ++k) {
        for (int l = 0; l < NL; ++l) {
            const float* bq = b_qkv + l*3*DM;

            // ---- phase A: Q gemv (t<256)  ||  K gemv (t>=256); prefetch V ----
            PFX pfV;
            if (t < 256) {
                gemv2x_m<RQ, DM, 256>(&g_wqX[l][r][0][0][0], xs[0], xs[1], part, t, pfQK);
                pfV = pfx_load<RQ, DM, 256>(&g_wvX[l][r][0][0][0], t);
            } else {
                gemv2x_m<RQ, DM, 256>(&g_wkX[l][r][0][0][0], xs[0], xs[1], part + 2048, t - 256, pfQK);
            }
            __syncthreads();

            // ---- phase B: V gemv (t<256)  ||  reduce Q+K (t>=256); K -> SMEM cache ----
            if (t < 256) {
                gemv2x_m<RQ, DM, 256>(&g_wvX[l][r][0][0][0], xs[0], xs[1], part + 4096, t, pfV);
            } else {
                int tl = t - 256;
                int m = tl >> 7, e = (tl >> 6) & 1, rr = tl & 63;
                const float* p = part + m*2048 + e*1024 + rr;
                float a = p[0];
                #pragma unroll
                for (int s = 1; s < 16; ++s) a += p[s*64];
                if (m == 0) { qs[e][rr] = a + bq[r*RQ + rr]; }
                else        { sm->kcs[l][e][rr][k] = a + bq[DM + r*RQ + rr]; }
            }
            __syncthreads();

            // ---- phase C: reduce V -> SMEM cache (t<128)  ||  scores from SMEM K (t>=256) ----
            if (t < 128) {
                int e = t >> 6, rr = t & 63;
                const float* p = part + 4096 + e*1024 + rr;
                float a = p[0];
                #pragma unroll
                for (int s = 1; s < 16; ++s) a += p[s*64];
                sm->vcs[l][e][k][rr] = a + bq[2*DM + r*RQ + rr];
            } else if (t >= 256) {
                int w2 = warp - 8;
                int e = w2 >> 2, hl = (w2 >> 1) & 1, half = w2 & 1;
                int p = half*32 + lane;
                if (p <= k) {
                    const float* kcol = &sm->kcs[l][e][hl*HDM][0];  // rows stride KP
                    const float* qv   = &qs[e][hl*HDM];
                    float dot = 0.f;
                    #pragma unroll
                    for (int d = 0; d < HDM; ++d)
                        dot = fmaf(kcol[d*KP + p], qv[d], dot);
                    sc[e][hl][p] = dot * scale;
                }
            }
            __syncthreads();

            // ---- phase D: per-warp redundant softmax + AV from SMEM V; prefetch O ----
            PFX pfO;
            {
                const int e   = warp >> 3;
                const int hl  = (warp >> 2) & 1;
                const int sub = warp & 3;
                float v0 = (lane      <= k) ? sc[e][hl][lane]      : -3.0e38f;
                float v1 = (lane + 32 <= k) ? sc[e][hl][lane + 32] : -3.0e38f;
                float mx = fmaxf(v0, v1);
                #pragma unroll
                for (int m = 16; m; m >>= 1) mx = fmaxf(mx, __shfl_xor_sync(0xffffffffu, mx, m));
                float e0 = (lane      <= k) ? expf(v0 - mx) : 0.f;
                float e1 = (lane + 32 <= k) ? expf(v1 - mx) : 0.f;
                float sum = e0 + e1;
                #pragma unroll
                for (int m = 16; m; m >>= 1) sum += __shfl_xor_sync(0xffffffffu, sum, m);
                float inv = 1.f / sum;
                sc2[warp][lane] = e0 * inv;
                if (lane < 16) sc2[warp][lane + 32] = e1 * inv;
                __syncwarp();
                const int offl = hl*HDM + lane;
                const float* vbase = &sm->vcs[l][e][0][0];
                float acc = 0.f;
                for (int p = sub; p <= k; p += 4)
                    acc = fmaf(sc2[warp][p], vbase[p*RQ + offl], acc);
                ctxp[sub][e][offl] = acc;
                pfO = pfx_load<DM, RQ, NTH>(&g_woX[l][r][0][0][0], t);
            }
            __syncthreads();
            // ---- combine sub-partials -> LOCAL ctx slice ----
            if (t < 128) {
                int e = t >> 6, rr = t & 63;
                ctx[e][rr] = ctxp[0][e][rr] + ctxp[1][e][rr] + ctxp[2][e][rr] + ctxp[3][e][rr];
            }
            __syncthreads();

            // ---- O column-slice GEMV on LOCAL ctx -> exchange partial sums ----
            gemv2x_m<DM, RQ, NTH>(&g_woX[l][r][0][0][0], ctx[0], ctx[1], part, t, pfO);
            __syncthreads();
            {
                int e = t >> 8, row = t & 255;
                const float* p = part + e*2048 + row;
                float a = p[0];
                #pragma unroll
                for (int s = 1; s < 8; ++s) a += p[s*DM];
                #pragma unroll
                for (int pr = 0; pr < CSZ; ++pr)
                    cl.map_shared_rank(&sm->opartA[0][0][0], pr)[r*2*DM + e*DM + row] = a;
            }
            CLUSTER_ARRIVE();
            PFX pfF1 = pfx_load<RF, DM, NTH>(&g_wff1X[l][r][0][0][0], t);   // in flight during rendezvous
            CLUSTER_WAIT();

            // ---- LN1: warp partials + single barrier + redundant final ----
            float vln;
            {
                int e = t >> 8, row = t & 255;
                vln = xs[e][row] + b_o[l*DM + row]
                    + opartA[0][e][row] + opartA[1][e][row]
                    + opartA[2][e][row] + opartA[3][e][row];
                float s1 = vln, s2 = vln*vln;
                #pragma unroll
                for (int m = 16; m; m >>= 1) {
                    s1 += __shfl_xor_sync(0xffffffffu, s1, m);
                    s2 += __shfl_xor_sync(0xffffffffu, s2, m);
                }
                if (lane == 0) { red[warp] = s1; red[16 + warp] = s2; }
            }
            __syncthreads();
            {
                int e = t >> 8, row = t & 255;
                float sum = 0.f, sq = 0.f;
                #pragma unroll
                for (int w = 0; w < 8; ++w) { sum += red[e*8 + w]; sq += red[16 + e*8 + w]; }
                float m   = sum * (1.f/256.f);
                float var = sq * (1.f/256.f) - m*m;
                xs[e][row] = (vln - m) * rsqrtf(var + 1e-5f) * ln1_g[l*DM + row] + ln1_b[l*DM + row];
            }
            __syncthreads();

            // ---- FF1 row-slice + GELU -> LOCAL ffs slice ----
            gemv2x_m<RF, DM, NTH>(&g_wff1X[l][r][0][0][0], xs[0], xs[1], part, t, pfF1);
            __syncthreads();
            {
                int e = t >> 8, rh = t & 255;
                float a = b_ff1[l*FFD + r*RF + rh];
                const float* p = part + e*2048 + rh;
                #pragma unroll
                for (int s = 0; s < 8; ++s) a += p[s*RF];
                ffsl[e][rh] = gelu_exact(a);
            }
            PFX pfF2 = pfx_load<DM, RF, NTH>(&g_wff2X[l][r][0][0][0], t);   // FIX: I = RF (local slice), not FFD
            __syncthreads();

            // ---- FF2 column-slice GEMV on LOCAL ffs -> exchange partial sums ----
            gemv2x_m<DM, RF, NTH>(&g_wff2X[l][r][0][0][0], ffsl[0], ffsl[1], part, t, pfF2);  // FIX: I = RF
            __syncthreads();
            {
                int e = t >> 8, row = t & 255;
                const float* p = part + e*2048 + row;
                float a = p[0];
                #pragma unroll
                for (int s = 1; s < 8; ++s) a += p[s*DM];
                #pragma unroll
                for (int pr = 0; pr < CSZ; ++pr)
                    cl.map_shared_rank(&sm->opartB[0][0][0], pr)[r*2*DM + e*DM + row] = a;
            }
            CLUSTER_ARRIVE();
            {   // next QKV prefetch + (last layer) p1 prefetch, in flight during rendezvous
                int lnext = (l + 1 == NL) ? 0 : l + 1;
                if (t < 256) pfQK = pfx_load<RQ, DM, 256>(&g_wqX[lnext][r][0][0][0], t);
                else         pfQK = pfx_load<RQ, DM, 256>(&g_wkX[lnext][r][0][0][0], t - 256);
                if (l == NL-1) pfP1 = pfx_load<128, DM, NTH>(&g_wp1X[0][0][0], t);
            }
            CLUSTER_WAIT();

            // ---- LN2: warp partials + single barrier + redundant final ----
            {
                int e = t >> 8, row = t & 255;
                vln = xs[e][row] + b_ff2[l*DM + row]
                    + opartB[0][e][row] + opartB[1][e][row]
                    + opartB[2][e][row] + opartB[3][e][row];
                float s1 = vln, s2 = vln*vln;
                #pragma unroll
                for (int m = 16; m; m >>= 1) {
                    s1 += __shfl_xor_sync(0xffffffffu, s1, m);
                    s2 += __shfl_xor_sync(0xffffffffu, s2, m);
                }
                if (lane == 0) { red[warp] = s1; red[16 + warp] = s2; }
            }
            __syncthreads();
            {
                int e = t >> 8, row = t & 255;
                float sum = 0.f, sq = 0.f;
                #pragma unroll
                for (int w = 0; w < 8; ++w) { sum += red[e*8 + w]; sq += red[16 + e*8 + w]; }
                float m   = sum * (1.f/256.f);
                float var = sq * (1.f/256.f) - m*m;
                xs[e][row] = (vln - m) * rsqrtf(var + 1e-5f) * ln2_g[l*DM + row] + ln2_b[l*DM + row];
                // stage next token's features during the last LN2
                if (l == NL-1 && t < 32 && k + 1 < NSEQ) {
                    int ee = t >> 4, j = t & 15;
                    xin[ee][j] = feat[((b0 + ee)*NSEQ + (k + 1))*16 + j];
                }
            }
            __syncthreads();
        }

        // ---- head: p1 fp16 f32x2 (redundant all ranks, prefetched) ----
        gemv2x_m<128, DM, NTH>(&g_wp1X[0][0][0], xs[0], xs[1], part, t, pfP1);
        __syncthreads();
        // ---- shadow phase: h1 reduce (t<256) || next-token delta-independent base (t>=256) ----
        if (t < 256) {
            int e = t >> 7, rh = t & 127;
            float a = b_p1[rh];
            const float* p = part + e*2048 + rh;
            #pragma unroll
            for (int s = 0; s < 16; ++s) a += p[s*128];
            h1[e][rh] = gelu_exact(a);
        } else if (k + 1 < NSEQ) {
            int tl = t - 256;
            #pragma unroll
            for (int i = 0; i < 2; ++i) {
                int idx = 2*tl + i;
                int e = idx >> 8, rr = idx & 255;
                float acc = b_in[rr];
                #pragma unroll
                for (int j = 0; j < 16; ++j) acc = fmaf(g_winT[j][rr], xin[e][j], acc);
                float dv  = expf((float)(rr & ~1) * PEC);
                float ang = (float)(k + 1) * dv;
                acc += (rr & 1) ? cosf(ang) : sinf(ang);
                part[4608 + idx] = acc;            // free region of part
            }
        }
        __syncthreads();
        // ---- p2 (redundant; delta needed locally by every rank) ----
        if (warp < 2) {
            float v = w_p2[lane]      * h1[warp][lane]
                    + w_p2[lane + 32] * h1[warp][lane + 32]
                    + w_p2[lane + 64] * h1[warp][lane + 64]
                    + w_p2[lane + 96] * h1[warp][lane + 96];
            #pragma unroll
            for (int m = 16; m; m >>= 1) v += __shfl_xor_sync(0xffffffffu, v, m);
            if (lane == 0) {
                float d = v + b_p2[0];
                if (r == 0) out[(b0 + warp)*NSEQ + k] = d;
                xin[warp][16] = d;
            }
        }
        __syncthreads();
        // ---- delta-add: x_{k+1} = base + W_in[:,16] * delta_k ----
        if (k + 1 < NSEQ) {
            int e = t >> 8, rr = t & 255;
            xs[e][rr] = part[4608 + t] + g_winT[16][rr] * xin[e][16];
        }
        __syncthreads();
    }
    cl.sync();   // no CTA exits while peer DSMEM traffic could be in flight
}

extern "C" void kernel_launch(void* const* d_in, const int* in_sizes, int n_in,
                              void* d_out, int out_size)
{
    const float* feat  = (const float*)d_in[0];
    const float* w_in  = (const float*)d_in[1];
    const float* b_in  = (const float*)d_in[2];
    const float* w_qkv = (const float*)d_in[3];
    const float* b_qkv = (const float*)d_in[4];
    const float* w_o   = (const float*)d_in[5];
    const float* b_o   = (const float*)d_in[6];
    const float* ln1_g = (const float*)d_in[7];
    const float* ln1_b = (const float*)d_in[8];
    const float* w_ff1 = (const float*)d_in[9];
    const float* b_ff1 = (const float*)d_in[10];
    const float* w_ff2 = (const float*)d_in[11];
    const float* b_ff2 = (const float*)d_in[12];
    const float* ln2_g = (const float*)d_in[13];
    const float* ln2_b = (const float*)d_in[14];
    const float* w_p1  = (const float*)d_in[15];
    const float* b_p1  = (const float*)d_in[16];
    const float* w_p2  = (const float*)d_in[17];
    const float* b_p2  = (const float*)d_in[18];
    float* out = (float*)d_out;

    static bool attr_set = false;
    if (!attr_set) {
        cudaFuncSetAttribute(hedge_kernel,
                             cudaFuncAttributeMaxDynamicSharedMemorySize,
                             (int)sizeof(SMem));
        attr_set = true;
    }

    prep_kernel<<<512, 256>>>(w_qkv, w_o, w_ff1, w_ff2, w_in, w_p1);
    hedge_kernel<<<(NB/2)*CSZ, NTH, sizeof(SMem)>>>(
        feat, b_in, b_qkv, b_o, ln1_g, ln1_b,
        b_ff1, b_ff2, ln2_g, ln2_b, b_p1, w_p2, b_p2, out);
}

// round 17
// speedup vs baseline: 1.0594x; 1.0594x over previous
#include <cuda_runtime.h>
#include <cuda_fp16.h>
#include <cooperative_groups.h>
#include <math.h>

namespace cg = cooperative_groups;

#define NL   3
#define NB   64
#define NSEQ 48
#define DM   256
#define HDM  32
#define FFD  1024
#define INP  17
#define NTH  512
#define CSZ  4     // CTAs per cluster
#define RQ   64    // DM rows (Q/K/V) per CTA; also O/FF2 column-slice width
#define RF   256   // FF1 rows per CTA
#define KP   49    // padded position stride for transposed K (odd -> conflict-free)

#define CLUSTER_ARRIVE() asm volatile("barrier.cluster.arrive.aligned;" ::: "memory")
#define CLUSTER_WAIT()   asm volatile("barrier.cluster.wait.aligned;" ::: "memory")

// ---------------- static device scratch (all big weights fp16) ----------------
__device__ __align__(16) __half g_wqT[NL][CSZ][DM][RQ];     // [j][row local]
__device__ __align__(16) __half g_wkT[NL][CSZ][DM][RQ];
__device__ __align__(16) __half g_wvT[NL][CSZ][DM][RQ];
__device__ __align__(16) __half g_woT[NL][CSZ][RQ][DM];     // column-slice: [j local ctx][row full]
__device__ __align__(16) __half g_wff1T[NL][CSZ][DM][RF];   // [j][row local]
__device__ __align__(16) __half g_wff2T[NL][CSZ][RF][DM];   // column-slice: [j local ffs][row full]
__device__ float g_winT[INP][DM];
__device__ __align__(16) __half g_wp1h[DM][128];

// ---------------- dynamic shared-memory layout (~196 KB) ----------------
struct SMem {
    alignas(16) float xs[2][DM];        // full x, replicated
    alignas(16) float qs[2][RQ];        // local q slice
    alignas(16) float ctx[2][RQ];       // LOCAL ctx slice only
    alignas(16) float ffsl[2][RF];      // LOCAL ffs slice only
    alignas(16) float part[6144];
    alignas(16) float opartA[CSZ][2][DM];  // O partial-sum exchange
    alignas(16) float opartB[CSZ][2][DM];  // FF2 partial-sum exchange
    alignas(16) float sc[2][2][NSEQ];
    alignas(16) float sc2[4][NSEQ];
    alignas(16) float h1[2][128];
    float xin[2][20];
    float red[64];
    // SMEM-resident KV cache: CTA r only ever touches dims [r*64, r*64+64).
    alignas(16) float kcs[NL][2][RQ][KP];     // K transposed: [local dim][pos], pos-stride 49
    alignas(16) float vcs[NL][2][NSEQ][RQ];   // V: [pos][local dim]
};

// ---------------- prep: transpose + split + fp16-convert ----------------
__global__ void prep_kernel(const float* __restrict__ w_qkv, const float* __restrict__ w_o,
                            const float* __restrict__ w_ff1, const float* __restrict__ w_ff2,
                            const float* __restrict__ w_in,  const float* __restrict__ w_p1)
{
    int tid = blockIdx.x * blockDim.x + threadIdx.x;
    int nth = gridDim.x * blockDim.x;

    for (int i = tid; i < NL*3*DM*DM; i += nth) {
        int l = i / (3*DM*DM); int rem = i - l*3*DM*DM; int row = rem / DM; int j = rem - row*DM;
        __half v = __float2half_rn(w_qkv[i]);
        int sel = row >> 8; int rr = row & 255;
        int r = rr >> 6; int rh = rr & 63;
        if (sel == 0)      g_wqT[l][r][j][rh] = v;
        else if (sel == 1) g_wkT[l][r][j][rh] = v;
        else               g_wvT[l][r][j][rh] = v;
    }
    for (int i = tid; i < NL*DM*DM; i += nth) {
        int l = i / (DM*DM); int rem = i - l*DM*DM; int row = rem / DM; int col = rem - row*DM;
        g_woT[l][col >> 6][col & 63][row] = __float2half_rn(w_o[i]);
    }
    for (int i = tid; i < NL*FFD*DM; i += nth) {
        int l = i / (FFD*DM); int rem = i - l*FFD*DM; int row = rem / DM; int j = rem - row*DM;
        g_wff1T[l][row >> 8][j][row & 255] = __float2half_rn(w_ff1[i]);
    }
    for (int i = tid; i < NL*DM*FFD; i += nth) {
        int l = i / (DM*FFD); int rem = i - l*DM*FFD; int row = rem / FFD; int col = rem - row*FFD;
        g_wff2T[l][col >> 8][col & 255][row] = __float2half_rn(w_ff2[i]);
    }
    for (int i = tid; i < DM*INP; i += nth) {
        int r = i / INP; int j = i - r*INP;
        g_winT[j][r] = w_in[i];
    }
    for (int i = tid; i < 128*DM; i += nth) {
        int row = i / DM; int j = i - row*DM;
        g_wp1h[j][row] = __float2half_rn(w_p1[i]);
    }
}

// load 4 half weights (one LDG.64) -> float4
__device__ __forceinline__ float4 ld4h(const uint2* p) {
    uint2 w = *p;
    __half2 a = *reinterpret_cast<__half2*>(&w.x);
    __half2 b = *reinterpret_cast<__half2*>(&w.y);
    float2 fa = __half22float2(a);
    float2 fb = __half22float2(b);
    float4 r; r.x = fa.x; r.y = fa.y; r.z = fb.x; r.w = fb.y;
    return r;
}
__device__ __forceinline__ float4 cvt4h(uint2 w) {
    __half2 a = *reinterpret_cast<__half2*>(&w.x);
    __half2 b = *reinterpret_cast<__half2*>(&w.y);
    float2 fa = __half22float2(a);
    float2 fb = __half22float2(b);
    float4 r; r.x = fa.x; r.y = fa.y; r.z = fb.x; r.w = fb.y;
    return r;
}

// ---------------- weight prefetch (issued BEFORE the barrier preceding a GEMV) ----
struct PF { uint2 a, b, c, d; };

template<int O, int I>
__device__ __forceinline__ PF pf_load(const __half* __restrict__ wT, int t) {
    constexpr int G = O / 4;
    constexpr int JC = I / (NTH / G);
    const int g = t % G;
    const int s = t / G;
    const uint2* wp = reinterpret_cast<const uint2*>(wT) + (size_t)(s * JC) * G + g;
    PF p; p.a = wp[0]; p.b = wp[G]; p.c = wp[2*G]; p.d = wp[3*G];
    return p;
}
// for the 256-thread O=64,I=256 sub-GEMV (G=16,S=16,JC=16)
__device__ __forceinline__ PF pf_load_h(const __half* __restrict__ wT, int tl) {
    const int g = tl & 15;
    const int s = tl >> 4;
    const uint2* wp = reinterpret_cast<const uint2*>(wT) + (size_t)(s * 16) * 16 + g;
    PF p; p.a = wp[0]; p.b = wp[16]; p.c = wp[32]; p.d = wp[48];
    return p;
}

#define FMA_BLOCK(w0,w1,w2,w3,av,bv)                                                        \
    ax=fmaf(w0.x,av.x,ax); ay=fmaf(w0.y,av.x,ay); az=fmaf(w0.z,av.x,az); aw=fmaf(w0.w,av.x,aw); \
    bx=fmaf(w0.x,bv.x,bx); by=fmaf(w0.y,bv.x,by); bz=fmaf(w0.z,bv.x,bz); bw=fmaf(w0.w,bv.x,bw); \
    ax=fmaf(w1.x,av.y,ax); ay=fmaf(w1.y,av.y,ay); az=fmaf(w1.z,av.y,az); aw=fmaf(w1.w,av.y,aw); \
    bx=fmaf(w1.x,bv.y,bx); by=fmaf(w1.y,bv.y,by); bz=fmaf(w1.z,bv.y,bz); bw=fmaf(w1.w,bv.y,bw); \
    ax=fmaf(w2.x,av.z,ax); ay=fmaf(w2.y,av.z,ay); az=fmaf(w2.z,av.z,az); aw=fmaf(w2.w,av.z,aw); \
    bx=fmaf(w2.x,bv.z,bx); by=fmaf(w2.y,bv.z,by); bz=fmaf(w2.z,bv.z,bz); bw=fmaf(w2.w,bv.z,bw); \
    ax=fmaf(w3.x,av.w,ax); ay=fmaf(w3.y,av.w,ay); az=fmaf(w3.z,av.w,az); aw=fmaf(w3.w,av.w,aw); \
    bx=fmaf(w3.x,bv.w,bx); by=fmaf(w3.y,bv.w,by); bz=fmaf(w3.z,bv.w,bz); bw=fmaf(w3.w,bv.w,bw);

// ---------------- dual-RHS GEMV (fp16 weights), 512 threads, prefetched u=0 ----
template<int O, int I>
__device__ __forceinline__ void gemv2h_m(const __half* __restrict__ wT,
                                         const float* __restrict__ x0,
                                         const float* __restrict__ x1,
                                         float* __restrict__ part, int t, const PF& pf)
{
    constexpr int G  = O / 4;
    constexpr int S  = NTH / G;
    constexpr int JC = I / S;
    const int g = t % G;
    const int s = t / G;
    const uint2*  __restrict__ w2  = reinterpret_cast<const uint2*>(wT);
    const float4* __restrict__ xa4 = reinterpret_cast<const float4*>(x0);
    const float4* __restrict__ xb4 = reinterpret_cast<const float4*>(x1);
    float ax=0.f, ay=0.f, az=0.f, aw=0.f;
    float bx=0.f, by=0.f, bz=0.f, bw=0.f;
    const int jb = s * JC;
    {
        float4 av = xa4[jb >> 2];
        float4 bv = xb4[jb >> 2];
        float4 w0 = cvt4h(pf.a);
        float4 w1 = cvt4h(pf.b);
        float4 w2v = cvt4h(pf.c);
        float4 w3 = cvt4h(pf.d);
        FMA_BLOCK(w0, w1, w2v, w3, av, bv)
    }
    #pragma unroll 2
    for (int u = 1; u < JC/4; ++u) {
        float4 av = xa4[(jb >> 2) + u];
        float4 bv = xb4[(jb >> 2) + u];
        const uint2* wp = w2 + (size_t)(jb + 4*u) * G + g;
        float4 w0 = ld4h(wp);
        float4 w1 = ld4h(wp + G);
        float4 w2v = ld4h(wp + 2*G);
        float4 w3 = ld4h(wp + 3*G);
        FMA_BLOCK(w0, w1, w2v, w3, av, bv)
    }
    float4 A; A.x=ax; A.y=ay; A.z=az; A.w=aw;
    float4 B; B.x=bx; B.y=by; B.z=bz; B.w=bw;
    reinterpret_cast<float4*>(part)[s*G + g]       = A;
    reinterpret_cast<float4*>(part)[512 + s*G + g] = B;
}

// ---------------- 256-thread dual-RHS fp16 GEMV (O=64, I=256), prefetched ----
__device__ __forceinline__ void gemv_halfh_m(const __half* __restrict__ wT,
                                             const float* __restrict__ x0,
                                             const float* __restrict__ x1,
                                             float* __restrict__ partf, int tl, const PF& pf)
{
    const int g = tl & 15;
    const int s = tl >> 4;
    const uint2*  __restrict__ w2  = reinterpret_cast<const uint2*>(wT);
    const float4* __restrict__ xa4 = reinterpret_cast<const float4*>(x0);
    const float4* __restrict__ xb4 = reinterpret_cast<const float4*>(x1);
    float ax=0.f, ay=0.f, az=0.f, aw=0.f;
    float bx=0.f, by=0.f, bz=0.f, bw=0.f;
    const int jb = s * 16;
    {
        float4 av = xa4[jb >> 2];
        float4 bv = xb4[jb >> 2];
        float4 w0 = cvt4h(pf.a);
        float4 w1 = cvt4h(pf.b);
        float4 w2v = cvt4h(pf.c);
        float4 w3 = cvt4h(pf.d);
        FMA_BLOCK(w0, w1, w2v, w3, av, bv)
    }
    #pragma unroll
    for (int u = 1; u < 4; ++u) {
        float4 av = xa4[(jb >> 2) + u];
        float4 bv = xb4[(jb >> 2) + u];
        const uint2* wp = w2 + (size_t)(jb + 4*u) * 16 + g;
        float4 w0 = ld4h(wp);
        float4 w1 = ld4h(wp + 16);
        float4 w2v = ld4h(wp + 32);
        float4 w3 = ld4h(wp + 48);
        FMA_BLOCK(w0, w1, w2v, w3, av, bv)
    }
    float4 A; A.x=ax; A.y=ay; A.z=az; A.w=aw;
    float4 B; B.x=bx; B.y=by; B.z=bz; B.w=bw;
    reinterpret_cast<float4*>(partf)[s*16 + g]       = A;
    reinterpret_cast<float4*>(partf)[256 + s*16 + g] = B;
}

__device__ __forceinline__ float gelu_exact(float x) {
    return 0.5f * x * (1.0f + erff(x * 0.70710678118654746f));
}

// ---------------- main: 4-CTA cluster per 2 batch elements ----------------
__global__ __launch_bounds__(NTH, 1) __cluster_dims__(CSZ, 1, 1)
void hedge_kernel(
    const float* __restrict__ feat,
    const float* __restrict__ b_in,
    const float* __restrict__ b_qkv,
    const float* __restrict__ b_o,
    const float* __restrict__ ln1_g, const float* __restrict__ ln1_b,
    const float* __restrict__ b_ff1, const float* __restrict__ b_ff2,
    const float* __restrict__ ln2_g, const float* __restrict__ ln2_b,
    const float* __restrict__ b_p1,
    const float* __restrict__ w_p2,  const float* __restrict__ b_p2,
    float* __restrict__ out)
{
    cg::cluster_group cl = cg::this_cluster();

    extern __shared__ __align__(16) char smem_raw[];
    SMem* sm = reinterpret_cast<SMem*>(smem_raw);
    float (&xs)[2][DM]        = sm->xs;
    float (&qs)[2][RQ]        = sm->qs;
    float (&ctx)[2][RQ]       = sm->ctx;
    float (&ffsl)[2][RF]      = sm->ffsl;
    float (&part)[6144]       = sm->part;
    float (&opartA)[CSZ][2][DM] = sm->opartA;
    float (&opartB)[CSZ][2][DM] = sm->opartB;
    float (&sc)[2][2][NSEQ]   = sm->sc;
    float (&sc2)[4][NSEQ]     = sm->sc2;
    float (&h1)[2][128]       = sm->h1;
    float (&xin)[2][20]       = sm->xin;
    float (&red)[64]          = sm->red;

    const int cid  = blockIdx.x >> 2;
    const int r    = blockIdx.x & 3;
    const int b0   = cid * 2;
    const int t    = threadIdx.x;
    const int lane = t & 31;
    const int warp = t >> 5;

    const float PEC   = -9.210340371976184f / 256.f;   // -ln(10000)/256
    const float scale = 0.17677669529663687f;          // 1/sqrt(32)

    __syncthreads();
    cl.sync();

    // ---- prologue: token 0 input (feat + PE; delta_0 = 0) ----
    if (t < 32) {
        int e = t >> 4, j = t & 15;
        xin[e][j] = feat[((b0 + e)*NSEQ + 0)*16 + j];
    }
    __syncthreads();
    {
        int e = t >> 8, rr = t & 255;
        float acc = b_in[rr];
        #pragma unroll
        for (int j = 0; j < 16; ++j) acc = fmaf(g_winT[j][rr], xin[e][j], acc);
        acc += (rr & 1) ? 1.0f : 0.0f;   // PE at pos 0
        xs[e][rr] = acc;
    }
    __syncthreads();

    // initial QKV weight prefetch for layer 0
    PF pfQK;
    if (t < 256) pfQK = pf_load_h(&g_wqT[0][r][0][0], t);
    else         pfQK = pf_load_h(&g_wkT[0][r][0][0], t - 256);
    PF pfP1;

    for (int k = 0; k < NSEQ; ++k) {
        for (int l = 0; l < NL; ++l) {
            const float* bq = b_qkv + l*3*DM;

            // ---- phase A: Q gemv (t<256)  ||  K gemv (t>=256); prefetch V ----
            PF pfV;
            if (t < 256) {
                gemv_halfh_m(&g_wqT[l][r][0][0], xs[0], xs[1], part, t, pfQK);
                pfV = pf_load_h(&g_wvT[l][r][0][0], t);
            } else {
                gemv_halfh_m(&g_wkT[l][r][0][0], xs[0], xs[1], part + 2048, t - 256, pfQK);
            }
            __syncthreads();

            // ---- phase B: V gemv (t<256)  ||  reduce Q+K (t>=256); K -> SMEM cache ----
            if (t < 256) {
                gemv_halfh_m(&g_wvT[l][r][0][0], xs[0], xs[1], part + 4096, t, pfV);
            } else {
                int tl = t - 256;
                int m = tl >> 7, e = (tl >> 6) & 1, rr = tl & 63;
                const float* p = part + m*2048 + e*1024 + rr;
                float a = p[0];
                #pragma unroll
                for (int s = 1; s < 16; ++s) a += p[s*64];
                if (m == 0) { qs[e][rr] = a + bq[r*RQ + rr]; }
                else        { sm->kcs[l][e][rr][k] = a + bq[DM + r*RQ + rr]; }
            }
            __syncthreads();

            // ---- phase C: reduce V -> SMEM cache (t<128)  ||  scores from SMEM K (t>=256) ----
            if (t < 128) {
                int e = t >> 6, rr = t & 63;
                const float* p = part + 4096 + e*1024 + rr;
                float a = p[0];
                #pragma unroll
                for (int s = 1; s < 16; ++s) a += p[s*64];
                sm->vcs[l][e][k][rr] = a + bq[2*DM + r*RQ + rr];
            } else if (t >= 256) {
                int w2 = warp - 8;
                int e = w2 >> 2, hl = (w2 >> 1) & 1, half = w2 & 1;
                int p = half*32 + lane;
                if (p <= k) {
                    const float* kcol = &sm->kcs[l][e][hl*HDM][0];  // rows stride KP
                    const float* qv   = &qs[e][hl*HDM];
                    float dot = 0.f;
                    #pragma unroll
                    for (int d = 0; d < HDM; ++d)
                        dot = fmaf(kcol[d*KP + p], qv[d], dot);
                    sc[e][hl][p] = dot * scale;
                }
            }
            __syncthreads();

            // ---- phase D: softmax + full AV by warps 0-3 (one per (e,hl)); all prefetch O ----
            PF pfO = pf_load<DM, RQ>(&g_woT[l][r][0][0], t);
            if (warp < 4) {
                const int e  = warp >> 1;
                const int hl = warp & 1;
                float v0 = (lane      <= k) ? sc[e][hl][lane]      : -3.0e38f;
                float v1 = (lane + 32 <= k) ? sc[e][hl][lane + 32] : -3.0e38f;
                float mx = fmaxf(v0, v1);
                #pragma unroll
                for (int m = 16; m; m >>= 1) mx = fmaxf(mx, __shfl_xor_sync(0xffffffffu, mx, m));
                float e0 = (lane      <= k) ? expf(v0 - mx) : 0.f;
                float e1 = (lane + 32 <= k) ? expf(v1 - mx) : 0.f;
                float sum = e0 + e1;
                #pragma unroll
                for (int m = 16; m; m >>= 1) sum += __shfl_xor_sync(0xffffffffu, sum, m);
                float inv = 1.f / sum;
                sc2[warp][lane] = e0 * inv;
                if (lane < 16) sc2[warp][lane + 32] = e1 * inv;
                __syncwarp();
                const int offl = hl*HDM + lane;
                const float* vbase = &sm->vcs[l][e][0][0];
                float acc0 = 0.f, acc1 = 0.f;
                int p = 0;
                for (; p + 1 <= k; p += 2) {
                    acc0 = fmaf(sc2[warp][p],     vbase[p*RQ + offl],     acc0);
                    acc1 = fmaf(sc2[warp][p + 1], vbase[(p+1)*RQ + offl], acc1);
                }
                if (p <= k) acc0 = fmaf(sc2[warp][p], vbase[p*RQ + offl], acc0);
                ctx[e][offl] = acc0 + acc1;
            }
            __syncthreads();

            // ---- O column-slice GEMV on LOCAL ctx -> exchange partial sums ----
            gemv2h_m<DM, RQ>(&g_woT[l][r][0][0], ctx[0], ctx[1], part, t, pfO);
            __syncthreads();
            {
                int e = t >> 8, row = t & 255;
                const float* p = part + e*2048 + row;
                float a = p[0];
                #pragma unroll
                for (int s = 1; s < 8; ++s) a += p[s*DM];
                #pragma unroll
                for (int pr = 0; pr < CSZ; ++pr)
                    cl.map_shared_rank(&sm->opartA[0][0][0], pr)[r*2*DM + e*DM + row] = a;
            }
            CLUSTER_ARRIVE();
            PF pfF1 = pf_load<RF, DM>(&g_wff1T[l][r][0][0], t);   // in flight during rendezvous
            CLUSTER_WAIT();

            // ---- LN1: warp partials + single barrier + redundant final ----
            float vln;
            {
                int e = t >> 8, row = t & 255;
                vln = xs[e][row] + b_o[l*DM + row]
                    + opartA[0][e][row] + opartA[1][e][row]
                    + opartA[2][e][row] + opartA[3][e][row];
                float s1 = vln, s2 = vln*vln;
                #pragma unroll
                for (int m = 16; m; m >>= 1) {
                    s1 += __shfl_xor_sync(0xffffffffu, s1, m);
                    s2 += __shfl_xor_sync(0xffffffffu, s2, m);
                }
                if (lane == 0) { red[warp] = s1; red[16 + warp] = s2; }
            }
            __syncthreads();
            {
                int e = t >> 8, row = t & 255;
                float sum = 0.f, sq = 0.f;
                #pragma unroll
                for (int w = 0; w < 8; ++w) { sum += red[e*8 + w]; sq += red[16 + e*8 + w]; }
                float m   = sum * (1.f/256.f);
                float var = sq * (1.f/256.f) - m*m;
                xs[e][row] = (vln - m) * rsqrtf(var + 1e-5f) * ln1_g[l*DM + row] + ln1_b[l*DM + row];
            }
            __syncthreads();

            // ---- FF1 row-slice + GELU -> LOCAL ffs slice ----
            gemv2h_m<RF, DM>(&g_wff1T[l][r][0][0], xs[0], xs[1], part, t, pfF1);
            __syncthreads();
            {
                int e = t >> 8, rh = t & 255;
                float a = b_ff1[l*FFD + r*RF + rh];
                const float* p = part + e*2048 + rh;
                #pragma unroll
                for (int s = 0; s < 8; ++s) a += p[s*RF];
                ffsl[e][rh] = gelu_exact(a);
            }
            PF pfF2 = pf_load<DM, RF>(&g_wff2T[l][r][0][0], t);
            __syncthreads();

            // ---- FF2 column-slice GEMV on LOCAL ffs -> exchange partial sums ----
            gemv2h_m<DM, RF>(&g_wff2T[l][r][0][0], ffsl[0], ffsl[1], part, t, pfF2);
            __syncthreads();
            {
                int e = t >> 8, row = t & 255;
                const float* p = part + e*2048 + row;
                float a = p[0];
                #pragma unroll
                for (int s = 1; s < 8; ++s) a += p[s*DM];
                #pragma unroll
                for (int pr = 0; pr < CSZ; ++pr)
                    cl.map_shared_rank(&sm->opartB[0][0][0], pr)[r*2*DM + e*DM + row] = a;
            }
            CLUSTER_ARRIVE();
            {   // next QKV prefetch + (last layer) p1 prefetch, in flight during rendezvous
                int lnext = (l + 1 == NL) ? 0 : l + 1;
                if (t < 256) pfQK = pf_load_h(&g_wqT[lnext][r][0][0], t);
                else         pfQK = pf_load_h(&g_wkT[lnext][r][0][0], t - 256);
                if (l == NL-1) pfP1 = pf_load<128, DM>(&g_wp1h[0][0], t);
            }
            CLUSTER_WAIT();

            // ---- LN2: warp partials + single barrier + redundant final ----
            {
                int e = t >> 8, row = t & 255;
                vln = xs[e][row] + b_ff2[l*DM + row]
                    + opartB[0][e][row] + opartB[1][e][row]
                    + opartB[2][e][row] + opartB[3][e][row];
                float s1 = vln, s2 = vln*vln;
                #pragma unroll
                for (int m = 16; m; m >>= 1) {
                    s1 += __shfl_xor_sync(0xffffffffu, s1, m);
                    s2 += __shfl_xor_sync(0xffffffffu, s2, m);
                }
                if (lane == 0) { red[warp] = s1; red[16 + warp] = s2; }
            }
            __syncthreads();
            {
                int e = t >> 8, row = t & 255;
                float sum = 0.f, sq = 0.f;
                #pragma unroll
                for (int w = 0; w < 8; ++w) { sum += red[e*8 + w]; sq += red[16 + e*8 + w]; }
                float m   = sum * (1.f/256.f);
                float var = sq * (1.f/256.f) - m*m;
                xs[e][row] = (vln - m) * rsqrtf(var + 1e-5f) * ln2_g[l*DM + row] + ln2_b[l*DM + row];
                // stage next token's features during the last LN2
                if (l == NL-1 && t < 32 && k + 1 < NSEQ) {
                    int ee = t >> 4, j = t & 15;
                    xin[ee][j] = feat[((b0 + ee)*NSEQ + (k + 1))*16 + j];
                }
            }
            __syncthreads();
        }

        // ---- head: p1 fp16 (redundant all ranks, prefetched) ----
        gemv2h_m<128, DM>(&g_wp1h[0][0], xs[0], xs[1], part, t, pfP1);
        __syncthreads();
        // ---- shadow phase: h1 reduce (t<256) || next-token delta-independent base (t>=256) ----
        if (t < 256) {
            int e = t >> 7, rh = t & 127;
            float a = b_p1[rh];
            const float* p = part + e*2048 + rh;
            #pragma unroll
            for (int s = 0; s < 16; ++s) a += p[s*128];
            h1[e][rh] = gelu_exact(a);
        } else if (k + 1 < NSEQ) {
            int tl = t - 256;
            #pragma unroll
            for (int i = 0; i < 2; ++i) {
                int idx = 2*tl + i;
                int e = idx >> 8, rr = idx & 255;
                float acc = b_in[rr];
                #pragma unroll
                for (int j = 0; j < 16; ++j) acc = fmaf(g_winT[j][rr], xin[e][j], acc);
                float dv  = expf((float)(rr & ~1) * PEC);
                float ang = (float)(k + 1) * dv;
                acc += (rr & 1) ? cosf(ang) : sinf(ang);
                part[4608 + idx] = acc;            // free region of part
            }
        }
        __syncthreads();
        // ---- p2 (redundant; delta needed locally by every rank) ----
        if (warp < 2) {
            float v = w_p2[lane]      * h1[warp][lane]
                    + w_p2[lane + 32] * h1[warp][lane + 32]
                    + w_p2[lane + 64] * h1[warp][lane + 64]
                    + w_p2[lane + 96] * h1[warp][lane + 96];
            #pragma unroll
            for (int m = 16; m; m >>= 1) v += __shfl_xor_sync(0xffffffffu, v, m);
            if (lane == 0) {
                float d = v + b_p2[0];
                if (r == 0) out[(b0 + warp)*NSEQ + k] = d;
                xin[warp][16] = d;
            }
        }
        __syncthreads();
        // ---- delta-add: x_{k+1} = base + W_in[:,16] * delta_k ----
        if (k + 1 < NSEQ) {
            int e = t >> 8, rr = t & 255;
            xs[e][rr] = part[4608 + t] + g_winT[16][rr] * xin[e][16];
        }
        __syncthreads();
    }
    cl.sync();   // no CTA exits while peer DSMEM traffic could be in flight
}

extern "C" void kernel_launch(void* const* d_in, const int* in_sizes, int n_in,
                              void* d_out, int out_size)
{
    const float* feat  = (const float*)d_in[0];
    const float* w_in  = (const float*)d_in[1];
    const float* b_in  = (const float*)d_in[2];
    const float* w_qkv = (const float*)d_in[3];
    const float* b_qkv = (const float*)d_in[4];
    const float* w_o   = (const float*)d_in[5];
    const float* b_o   = (const float*)d_in[6];
    const float* ln1_g = (const float*)d_in[7];
    const float* ln1_b = (const float*)d_in[8];
    const float* w_ff1 = (const float*)d_in[9];
    const float* b_ff1 = (const float*)d_in[10];
    const float* w_ff2 = (const float*)d_in[11];
    const float* b_ff2 = (const float*)d_in[12];
    const float* ln2_g = (const float*)d_in[13];
    const float* ln2_b = (const float*)d_in[14];
    const float* w_p1  = (const float*)d_in[15];
    const float* b_p1  = (const float*)d_in[16];
    const float* w_p2  = (const float*)d_in[17];
    const float* b_p2  = (const float*)d_in[18];
    float* out = (float*)d_out;

    static bool attr_set = false;
    if (!attr_set) {
        cudaFuncSetAttribute(hedge_kernel,
                             cudaFuncAttributeMaxDynamicSharedMemorySize,
                             (int)sizeof(SMem));
        attr_set = true;
    }

    prep_kernel<<<512, 256>>>(w_qkv, w_o, w_ff1, w_ff2, w_in, w_p1);
    hedge_kernel<<<(NB/2)*CSZ, NTH, sizeof(SMem)>>>(
        feat, b_in, b_qkv, b_o, ln1_g, ln1_b,
        b_ff1, b_ff2, ln2_g, ln2_b, b_p1, w_p2, b_p2, out);
}